// round 4
// baseline (speedup 1.0000x reference)
#include <cuda_runtime.h>
#include <cuda_bf16.h>
#include <cstdint>
#include <cstddef>

// Problem sizes (fixed by the reference)
#define M_TOTAL 65536   // 8 * 8192
#define KF      512     // in_features (fp32 K)
#define KB      1024    // bf16 K after hi/lo split
#define NF      512     // out_features
#define W_ELEMS (KF * NF)  // 262144

// ---------------------------------------------------------------------------
// Device-global scratch (allocation-free contract: __device__ globals only)
// ---------------------------------------------------------------------------
__device__ double g_sum_w;
__device__ double g_sum_absw;
// Sign matrix, transposed + K-duplicated for the split GEMM:
// g_Bt[n][2k] = g_Bt[n][2k+1] = sign(W[k][n] - mean(W))  (bf16, exactly +-1 or 0)
__device__ __nv_bfloat16 g_Bt[NF * KB];

// ---------------------------------------------------------------------------
// Kernel 1: zero the fp64 accumulators (graph replays reuse globals!)
// ---------------------------------------------------------------------------
__global__ void zero_stats_kernel() {
    g_sum_w = 0.0;
    g_sum_absw = 0.0;
}

// ---------------------------------------------------------------------------
// Kernel 2: fp64 reduce of sum(W) and sum(|W|) over 262144 elems
// 256 blocks x 256 threads, 4 elems/thread
// ---------------------------------------------------------------------------
__global__ void reduce_w_kernel(const float* __restrict__ w) {
    int tid = threadIdx.x;
    int base = blockIdx.x * 1024 + tid;
    double s = 0.0, sa = 0.0;
#pragma unroll
    for (int j = 0; j < 4; ++j) {
        float v = w[base + j * 256];
        s  += (double)v;
        sa += (double)fabsf(v);
    }
#pragma unroll
    for (int off = 16; off > 0; off >>= 1) {
        s  += __shfl_down_sync(0xffffffffu, s,  off);
        sa += __shfl_down_sync(0xffffffffu, sa, off);
    }
    __shared__ double sh_s[8], sh_sa[8];
    int wid = tid >> 5, lane = tid & 31;
    if (lane == 0) { sh_s[wid] = s; sh_sa[wid] = sa; }
    __syncthreads();
    if (tid == 0) {
        double ts = 0.0, tsa = 0.0;
#pragma unroll
        for (int i = 0; i < 8; ++i) { ts += sh_s[i]; tsa += sh_sa[i]; }
        atomicAdd(&g_sum_w, ts);
        atomicAdd(&g_sum_absw, tsa);
    }
}

// ---------------------------------------------------------------------------
// Kernel 3: build transposed, K-duplicated sign matrix in bf16
// W is [K=512][N=512] row-major.
// ---------------------------------------------------------------------------
__global__ void build_bt_kernel(const float* __restrict__ w) {
    int idx = blockIdx.x * blockDim.x + threadIdx.x;   // 0..262143
    float mean = (float)(g_sum_w * (1.0 / 262144.0));
    float d = w[idx] - mean;
    float s = (d > 0.0f) ? 1.0f : ((d < 0.0f) ? -1.0f : 0.0f);
    __nv_bfloat16 bs = __float2bfloat16_rn(s);
    int k = idx >> 9;      // in-feature index
    int n = idx & 511;     // out-feature index
    g_Bt[n * KB + 2 * k]     = bs;
    g_Bt[n * KB + 2 * k + 1] = bs;
}

// ---------------------------------------------------------------------------
// Quantization epilogue: mirrors reference arithmetic exactly
//   t = clip(y, -1, 1); q = round(t*7)/7 (round-half-even); out = y + (q - y)
// ---------------------------------------------------------------------------
__device__ __forceinline__ float quant_out(float y) {
    float t = fminf(fmaxf(y, -1.0f), 1.0f);
    float q = rintf(t * 7.0f) / 7.0f;
    return y + (q - y);
}

// ---------------------------------------------------------------------------
// Kernel 4: split-bf16 GEMM + quant epilogue.
//   y[m][n] = gamma * sum_k x[m][k] * S[k][n]  + bias[n]
//   x split on the fly into (hi, lo) bf16 pairs -> effective K = 1024.
// CTA tile: 128(M) x 128(N) x 32(bf16 K) per iter, 32 iters.
// 8 warps, warp tile 32(M) x 64(N), mma.sync.m16n8k16 bf16.
// ---------------------------------------------------------------------------
__global__ __launch_bounds__(256, 2)
void bitlinear_gemm_kernel(const float* __restrict__ x,
                           const float* __restrict__ bias,
                           float* __restrict__ out) {
    // Padded smem: 16 data u32 (= 32 bf16) + 4 pad per row -> conflict-free frags
    __shared__ uint32_t As[128][20];
    __shared__ uint32_t Bs[128][20];

    int bid = blockIdx.x;         // 2048 blocks; n-tile fastest for L2 x-reuse
    int m0 = (bid >> 2) << 7;     // (bid/4)*128
    int n0 = (bid & 3) << 7;      // (bid%4)*128

    int tid   = threadIdx.x;
    int wid   = tid >> 5;
    int lane  = tid & 31;
    int wm    = wid & 3;          // warp m-tile: rows wm*32 .. +31
    int wn    = wid >> 2;         // warp n-tile: cols wn*64 .. +63
    int group = lane >> 2;        // 0..7
    int tq    = lane & 3;         // 0..3

    float acc[2][8][4];
#pragma unroll
    for (int i = 0; i < 2; ++i)
#pragma unroll
        for (int j = 0; j < 8; ++j)
#pragma unroll
            for (int r = 0; r < 4; ++r) acc[i][j][r] = 0.0f;

    // A loader: thread -> (row = tid/2, 8 fp32 cols at (tid&1)*8)
    int arow    = tid >> 1;
    int acolseg = tid & 1;
    const float* xg = x + (size_t)(m0 + arow) * KF + acolseg * 8;

    // B loader: thread -> (n-row = tid/2, two uint4 segments)
    int brow = tid >> 1;
    int bseg = tid & 1;
    const __nv_bfloat16* btg = g_Bt + (size_t)(n0 + brow) * KB;

    for (int kt = 0; kt < 32; ++kt) {
        // ---- global loads (issue before sync) ----
        const float4* xg4 = (const float4*)(xg + kt * 16);
        float4 f0 = xg4[0];
        float4 f1 = xg4[1];
        const uint4* bg4 = (const uint4*)(btg + kt * 32);
        uint4 bv0 = bg4[bseg * 2];
        uint4 bv1 = bg4[bseg * 2 + 1];

        // ---- fp32 -> (hi, lo) bf16 split, packed per fp32 lane ----
        uint32_t ap[8];
        float fv[8] = {f0.x, f0.y, f0.z, f0.w, f1.x, f1.y, f1.z, f1.w};
#pragma unroll
        for (int c = 0; c < 8; ++c) {
            float v = fv[c];
            __nv_bfloat16 h = __float2bfloat16_rn(v);
            float r = v - __bfloat162float(h);   // exact residual
            __nv_bfloat16 l = __float2bfloat16_rn(r);
            ap[c] = ((uint32_t)__bfloat16_as_ushort(l) << 16) |
                    (uint32_t)__bfloat16_as_ushort(h);
        }

        __syncthreads();   // previous iteration's smem reads complete

        uint4* as4 = (uint4*)(&As[arow][acolseg * 8]);
        as4[0] = make_uint4(ap[0], ap[1], ap[2], ap[3]);
        as4[1] = make_uint4(ap[4], ap[5], ap[6], ap[7]);
        uint4* bs4 = (uint4*)(&Bs[brow][0]);
        bs4[bseg * 2]     = bv0;
        bs4[bseg * 2 + 1] = bv1;

        __syncthreads();

        // ---- compute: 2 k16 steps x (2 m-tiles x 8 n-tiles) mma ----
#pragma unroll
        for (int s = 0; s < 2; ++s) {
            uint32_t af[2][4];
#pragma unroll
            for (int mt = 0; mt < 2; ++mt) {
                int r0 = wm * 32 + mt * 16 + group;
                af[mt][0] = As[r0][s * 8 + tq];
                af[mt][1] = As[r0 + 8][s * 8 + tq];
                af[mt][2] = As[r0][s * 8 + 4 + tq];
                af[mt][3] = As[r0 + 8][s * 8 + 4 + tq];
            }
#pragma unroll
            for (int nt = 0; nt < 8; ++nt) {
                int nr = wn * 64 + nt * 8 + group;
                uint32_t bf0 = Bs[nr][s * 8 + tq];
                uint32_t bf1 = Bs[nr][s * 8 + 4 + tq];
#pragma unroll
                for (int mt = 0; mt < 2; ++mt) {
                    asm volatile(
                        "mma.sync.aligned.m16n8k16.row.col.f32.bf16.bf16.f32 "
                        "{%0,%1,%2,%3}, {%4,%5,%6,%7}, {%8,%9}, {%0,%1,%2,%3};\n"
                        : "+f"(acc[mt][nt][0]), "+f"(acc[mt][nt][1]),
                          "+f"(acc[mt][nt][2]), "+f"(acc[mt][nt][3])
                        : "r"(af[mt][0]), "r"(af[mt][1]),
                          "r"(af[mt][2]), "r"(af[mt][3]),
                          "r"(bf0), "r"(bf1));
                }
            }
        }
    }

    // ---- epilogue: scale by gamma, add bias, quantize, store ----
    float gamma = (float)(g_sum_absw * (1.0 / 262144.0));
#pragma unroll
    for (int mt = 0; mt < 2; ++mt) {
#pragma unroll
        for (int nt = 0; nt < 8; ++nt) {
            int row = m0 + wm * 32 + mt * 16 + group;
            int col = n0 + wn * 64 + nt * 8 + tq * 2;
            float bv0 = bias[col];
            float bv1 = bias[col + 1];
            float y0 = gamma * acc[mt][nt][0] + bv0;
            float y1 = gamma * acc[mt][nt][1] + bv1;
            float y2 = gamma * acc[mt][nt][2] + bv0;
            float y3 = gamma * acc[mt][nt][3] + bv1;
            float2* o0 = (float2*)(out + (size_t)row * NF + col);
            *o0 = make_float2(quant_out(y0), quant_out(y1));
            float2* o1 = (float2*)(out + (size_t)(row + 8) * NF + col);
            *o1 = make_float2(quant_out(y2), quant_out(y3));
        }
    }
}

// ---------------------------------------------------------------------------
// Launch: zero stats -> fp64 reduce -> build sign matrix -> GEMM+quant
// All plain kernel launches, graph-capturable, no allocations.
// ---------------------------------------------------------------------------
extern "C" void kernel_launch(void* const* d_in, const int* in_sizes, int n_in,
                              void* d_out, int out_size) {
    const float* x = nullptr;
    const float* w = nullptr;
    const float* b = nullptr;
    for (int i = 0; i < n_in; ++i) {
        if (in_sizes[i] == M_TOTAL * KF)      x = (const float*)d_in[i];
        else if (in_sizes[i] == W_ELEMS)      w = (const float*)d_in[i];
        else if (in_sizes[i] == NF)           b = (const float*)d_in[i];
    }
    float* out = (float*)d_out;

    zero_stats_kernel<<<1, 1>>>();
    reduce_w_kernel<<<256, 256>>>(w);
    build_bt_kernel<<<W_ELEMS / 256, 256>>>(w);
    bitlinear_gemm_kernel<<<(M_TOTAL / 128) * (NF / 128), 256>>>(x, b, out);
}

// round 7
// speedup vs baseline: 1.2007x; 1.2007x over previous
#include <cuda_runtime.h>
#include <cuda_bf16.h>
#include <cstdint>
#include <cstddef>

// Problem sizes (fixed by the reference)
#define M_TOTAL 65536   // 8 * 8192
#define KF      512     // in_features (fp32 K)
#define KB      1024    // bf16 K after hi/lo split
#define NF      512     // out_features
#define W_ELEMS (KF * NF)  // 262144

// ---------------------------------------------------------------------------
// Device-global scratch (allocation-free contract: __device__ globals only)
// ---------------------------------------------------------------------------
__device__ double g_sum_w;
__device__ double g_sum_absw;
// Sign matrix, transposed + K-duplicated for the split GEMM:
// g_Bt[n][2k] = g_Bt[n][2k+1] = sign(W[k][n] - mean(W))  (bf16, exactly +-1 or 0)
__device__ __nv_bfloat16 g_Bt[NF * KB];

// ---------------------------------------------------------------------------
// Kernel 1: zero the fp64 accumulators (graph replays reuse globals!)
// ---------------------------------------------------------------------------
__global__ void zero_stats_kernel() {
    g_sum_w = 0.0;
    g_sum_absw = 0.0;
}

// ---------------------------------------------------------------------------
// Kernel 2: fp64 reduce of sum(W) and sum(|W|) over 262144 elems
// ---------------------------------------------------------------------------
__global__ void reduce_w_kernel(const float* __restrict__ w) {
    int tid = threadIdx.x;
    int base = blockIdx.x * 1024 + tid;
    double s = 0.0, sa = 0.0;
#pragma unroll
    for (int j = 0; j < 4; ++j) {
        float v = w[base + j * 256];
        s  += (double)v;
        sa += (double)fabsf(v);
    }
#pragma unroll
    for (int off = 16; off > 0; off >>= 1) {
        s  += __shfl_down_sync(0xffffffffu, s,  off);
        sa += __shfl_down_sync(0xffffffffu, sa, off);
    }
    __shared__ double sh_s[8], sh_sa[8];
    int wid = tid >> 5, lane = tid & 31;
    if (lane == 0) { sh_s[wid] = s; sh_sa[wid] = sa; }
    __syncthreads();
    if (tid == 0) {
        double ts = 0.0, tsa = 0.0;
#pragma unroll
        for (int i = 0; i < 8; ++i) { ts += sh_s[i]; tsa += sh_sa[i]; }
        atomicAdd(&g_sum_w, ts);
        atomicAdd(&g_sum_absw, tsa);
    }
}

// ---------------------------------------------------------------------------
// Kernel 3: build transposed, K-duplicated sign matrix in bf16
// ---------------------------------------------------------------------------
__global__ void build_bt_kernel(const float* __restrict__ w) {
    int idx = blockIdx.x * blockDim.x + threadIdx.x;   // 0..262143
    float mean = (float)(g_sum_w * (1.0 / 262144.0));
    float d = w[idx] - mean;
    float s = (d > 0.0f) ? 1.0f : ((d < 0.0f) ? -1.0f : 0.0f);
    __nv_bfloat16 bs = __float2bfloat16_rn(s);
    int k = idx >> 9;      // in-feature index
    int n = idx & 511;     // out-feature index
    g_Bt[n * KB + 2 * k]     = bs;
    g_Bt[n * KB + 2 * k + 1] = bs;
}

// ---------------------------------------------------------------------------
// Quantization epilogue: mirrors reference arithmetic exactly
// ---------------------------------------------------------------------------
__device__ __forceinline__ float quant_out(float y) {
    float t = fminf(fmaxf(y, -1.0f), 1.0f);
    float q = rintf(t * 7.0f) / 7.0f;
    return y + (q - y);
}

// ---------------------------------------------------------------------------
// Kernel 4: split-bf16 GEMM + quant epilogue.
//   CTA tile 128x128x32(bf16 K), 2-stage smem ping-pong, 1 sync/iter.
//   ldmatrix.x4 fragment loads, cp.async for B, register-staged A w/ on-the-fly
//   fp32 -> (hi,lo) bf16 split. 8 warps, warp tile 32x64, mma.m16n8k16 bf16.
// ---------------------------------------------------------------------------
__global__ __launch_bounds__(256, 2)
void bitlinear_gemm_kernel(const float* __restrict__ x,
                           const float* __restrict__ bias,
                           float* __restrict__ out) {
    // Padded rows: 16 data u32 (=32 bf16) + 4 pad -> conflict-free LDSM phases
    __shared__ uint32_t As[2][128][20];
    __shared__ uint32_t Bs[2][128][20];

    int bid = blockIdx.x;         // n-tile fastest for L2 x-reuse
    int m0 = (bid >> 2) << 7;
    int n0 = (bid & 3) << 7;

    int tid   = threadIdx.x;
    int wid   = tid >> 5;
    int lane  = tid & 31;
    int wm    = wid & 3;          // warp m-tile: rows wm*32 .. +31
    int wn    = wid >> 2;         // warp n-tile: cols wn*64 .. +63
    int group = lane >> 2;        // 0..7
    int tq    = lane & 3;         // 0..3

    float acc[2][8][4];
#pragma unroll
    for (int i = 0; i < 2; ++i)
#pragma unroll
        for (int j = 0; j < 8; ++j)
#pragma unroll
            for (int r = 0; r < 4; ++r) acc[i][j][r] = 0.0f;

    // ---- loader mappings ----
    int arow    = tid >> 1;            // A: row, and which 8-fp32 segment
    int acolseg = tid & 1;
    const float* xg = x + (size_t)(m0 + arow) * KF + acolseg * 8;

    int brow = tid >> 1;               // B: row (n index), 2x16B chunks
    int bseg = tid & 1;
    const __nv_bfloat16* btg = g_Bt + (size_t)(n0 + brow) * KB + bseg * 16;

    uint32_t As_base = (uint32_t)__cvta_generic_to_shared(&As[0][0][0]);
    uint32_t Bs_base = (uint32_t)__cvta_generic_to_shared(&Bs[0][0][0]);
    const uint32_t STAGE = 128 * 20 * 4;   // bytes per stage

    // A store address (u32 index within stage)
    uint32_t a_st = (uint32_t)(arow * 20 + acolseg * 8) * 4;
    // B cp.async dst addresses (two 16B chunks per thread)
    uint32_t b_st0 = (uint32_t)(brow * 20 + bseg * 8) * 4;
    uint32_t b_st1 = b_st0 + 16;

    // ldmatrix lane address patterns (u32 col units; row within CTA tile)
    int a_lm_row = wm * 32 + (lane & 7) + ((lane >> 3) & 1) * 8;  // + mt*16
    int a_lm_col = (lane >> 4) * 4;                                // + s*8
    int b_lm_row = wn * 64 + ((lane >> 4) & 1) * 8 + (lane & 7);   // + ntp*16
    int b_lm_col = ((lane >> 3) & 1) * 4;                          // + s*8

    // ---- prologue: fill stage 0 ----
    {
        const float4* xg4 = (const float4*)xg;
        float4 f0 = xg4[0];
        float4 f1 = xg4[1];
        // B via cp.async into stage 0
        asm volatile("cp.async.cg.shared.global [%0], [%1], 16;\n"
                     :: "r"(Bs_base + b_st0), "l"(btg));
        asm volatile("cp.async.cg.shared.global [%0], [%1], 16;\n"
                     :: "r"(Bs_base + b_st1), "l"(btg + 8));
        asm volatile("cp.async.commit_group;\n");
        uint32_t ap[8];
        float fv[8] = {f0.x, f0.y, f0.z, f0.w, f1.x, f1.y, f1.z, f1.w};
#pragma unroll
        for (int c = 0; c < 8; ++c) {
            float v = fv[c];
            __nv_bfloat16 h = __float2bfloat16_rn(v);
            float r = v - __bfloat162float(h);
            __nv_bfloat16 l = __float2bfloat16_rn(r);
            ap[c] = ((uint32_t)__bfloat16_as_ushort(l) << 16) |
                    (uint32_t)__bfloat16_as_ushort(h);
        }
        uint4* as4 = (uint4*)(&As[0][arow][acolseg * 8]);
        as4[0] = make_uint4(ap[0], ap[1], ap[2], ap[3]);
        as4[1] = make_uint4(ap[4], ap[5], ap[6], ap[7]);
    }

    for (int kt = 0; kt < 32; ++kt) {
        int cur = kt & 1;
        int nxt = cur ^ 1;
        uint32_t a_base = As_base + cur * STAGE;
        uint32_t b_base = Bs_base + cur * STAGE;

        asm volatile("cp.async.wait_group 0;\n" ::: "memory");
        __syncthreads();   // stage `cur` ready; prior reads of `nxt` done

        // ---- issue next iteration's global loads early ----
        float4 f0, f1;
        if (kt < 31) {
            const float4* xg4 = (const float4*)(xg + (kt + 1) * 16);
            f0 = xg4[0];
            f1 = xg4[1];
            const __nv_bfloat16* bg = btg + (size_t)(kt + 1) * 32;
            uint32_t bdst = Bs_base + nxt * STAGE;
            asm volatile("cp.async.cg.shared.global [%0], [%1], 16;\n"
                         :: "r"(bdst + b_st0), "l"(bg));
            asm volatile("cp.async.cg.shared.global [%0], [%1], 16;\n"
                         :: "r"(bdst + b_st1), "l"(bg + 8));
            asm volatile("cp.async.commit_group;\n");
        }

        // ---- compute: 2 k16 steps ----
#pragma unroll
        for (int s = 0; s < 2; ++s) {
            uint32_t af[2][4];
#pragma unroll
            for (int mt = 0; mt < 2; ++mt) {
                uint32_t addr = a_base +
                    (uint32_t)((a_lm_row + mt * 16) * 20 + a_lm_col + s * 8) * 4;
                asm volatile(
                    "ldmatrix.sync.aligned.m8n8.x4.shared.b16 {%0,%1,%2,%3}, [%4];\n"
                    : "=r"(af[mt][0]), "=r"(af[mt][1]),
                      "=r"(af[mt][2]), "=r"(af[mt][3])
                    : "r"(addr));
            }
            uint32_t bf[8][2];
#pragma unroll
            for (int ntp = 0; ntp < 4; ++ntp) {
                uint32_t addr = b_base +
                    (uint32_t)((b_lm_row + ntp * 16) * 20 + b_lm_col + s * 8) * 4;
                uint32_t r0, r1, r2, r3;
                asm volatile(
                    "ldmatrix.sync.aligned.m8n8.x4.shared.b16 {%0,%1,%2,%3}, [%4];\n"
                    : "=r"(r0), "=r"(r1), "=r"(r2), "=r"(r3)
                    : "r"(addr));
                bf[2 * ntp][0]     = r0;  // nt even: k0-7
                bf[2 * ntp][1]     = r1;  // nt even: k8-15
                bf[2 * ntp + 1][0] = r2;  // nt odd
                bf[2 * ntp + 1][1] = r3;
            }
#pragma unroll
            for (int nt = 0; nt < 8; ++nt) {
#pragma unroll
                for (int mt = 0; mt < 2; ++mt) {
                    asm volatile(
                        "mma.sync.aligned.m16n8k16.row.col.f32.bf16.bf16.f32 "
                        "{%0,%1,%2,%3}, {%4,%5,%6,%7}, {%8,%9}, {%0,%1,%2,%3};\n"
                        : "+f"(acc[mt][nt][0]), "+f"(acc[mt][nt][1]),
                          "+f"(acc[mt][nt][2]), "+f"(acc[mt][nt][3])
                        : "r"(af[mt][0]), "r"(af[mt][1]),
                          "r"(af[mt][2]), "r"(af[mt][3]),
                          "r"(bf[nt][0]), "r"(bf[nt][1]));
                }
            }
        }

        // ---- convert + store A for next iteration into stage `nxt` ----
        if (kt < 31) {
            uint32_t ap[8];
            float fv[8] = {f0.x, f0.y, f0.z, f0.w, f1.x, f1.y, f1.z, f1.w};
#pragma unroll
            for (int c = 0; c < 8; ++c) {
                float v = fv[c];
                __nv_bfloat16 h = __float2bfloat16_rn(v);
                float r = v - __bfloat162float(h);
                __nv_bfloat16 l = __float2bfloat16_rn(r);
                ap[c] = ((uint32_t)__bfloat16_as_ushort(l) << 16) |
                        (uint32_t)__bfloat16_as_ushort(h);
            }
            uint4* as4 = (uint4*)(&As[nxt][arow][acolseg * 8]);
            as4[0] = make_uint4(ap[0], ap[1], ap[2], ap[3]);
            as4[1] = make_uint4(ap[4], ap[5], ap[6], ap[7]);
        }
    }

    // ---- epilogue: scale by gamma, add bias, quantize, store ----
    float gamma = (float)(g_sum_absw * (1.0 / 262144.0));
#pragma unroll
    for (int mt = 0; mt < 2; ++mt) {
#pragma unroll
        for (int nt = 0; nt < 8; ++nt) {
            int row = m0 + wm * 32 + mt * 16 + group;
            int col = n0 + wn * 64 + nt * 8 + tq * 2;
            float bv0 = bias[col];
            float bv1 = bias[col + 1];
            float y0 = gamma * acc[mt][nt][0] + bv0;
            float y1 = gamma * acc[mt][nt][1] + bv1;
            float y2 = gamma * acc[mt][nt][2] + bv0;
            float y3 = gamma * acc[mt][nt][3] + bv1;
            float2* o0 = (float2*)(out + (size_t)row * NF + col);
            *o0 = make_float2(quant_out(y0), quant_out(y1));
            float2* o1 = (float2*)(out + (size_t)(row + 8) * NF + col);
            *o1 = make_float2(quant_out(y2), quant_out(y3));
        }
    }
}

// ---------------------------------------------------------------------------
// Launch: zero stats -> fp64 reduce -> build sign matrix -> GEMM+quant
// ---------------------------------------------------------------------------
extern "C" void kernel_launch(void* const* d_in, const int* in_sizes, int n_in,
                              void* d_out, int out_size) {
    const float* x = nullptr;
    const float* w = nullptr;
    const float* b = nullptr;
    for (int i = 0; i < n_in; ++i) {
        if (in_sizes[i] == M_TOTAL * KF)      x = (const float*)d_in[i];
        else if (in_sizes[i] == W_ELEMS)      w = (const float*)d_in[i];
        else if (in_sizes[i] == NF)           b = (const float*)d_in[i];
    }
    float* out = (float*)d_out;

    zero_stats_kernel<<<1, 1>>>();
    reduce_w_kernel<<<256, 256>>>(w);
    build_bt_kernel<<<W_ELEMS / 256, 256>>>(w);
    bitlinear_gemm_kernel<<<(M_TOTAL / 128) * (NF / 128), 256>>>(x, b, out);
}

// round 11
// speedup vs baseline: 1.3907x; 1.1583x over previous
#include <cuda_runtime.h>
#include <cuda_bf16.h>
#include <cstdint>
#include <cstddef>

// Problem sizes (fixed by the reference)
#define M_TOTAL 65536   // 8 * 8192
#define KF      512     // in_features (fp32 K)
#define NF      512     // out_features
#define W_ELEMS (KF * NF)  // 262144

// GEMM tiling: CTA 128x128, per-iter 32 fp32 k (2 k16 steps, hi+lo passes)
#define N_ITERS 16

// Dynamic smem layout (bytes). Row stride 80B (16 data u32 + 4 pad u32).
#define ROWB     80
#define PLANE_B  (128 * ROWB)              // 10240
#define SA_OFF(stage, plane) (((stage) * 2 + (plane)) * PLANE_B)
#define SB_OFF(stage)        (40960 + (stage) * PLANE_B)
#define SM_TOTAL             61440

// ---------------------------------------------------------------------------
// Device-global scratch (allocation-free contract: __device__ globals only)
// ---------------------------------------------------------------------------
__device__ double g_sum_w;
__device__ double g_sum_absw;
// Sign matrix, transposed, NOT K-duplicated: g_Bt[n][k] = sign(W[k][n]-mean)
__device__ __align__(16) __nv_bfloat16 g_Bt[NF * KF];

// ---------------------------------------------------------------------------
// Kernel 1: zero the fp64 accumulators (graph replays reuse globals!)
// ---------------------------------------------------------------------------
__global__ void zero_stats_kernel() {
    g_sum_w = 0.0;
    g_sum_absw = 0.0;
}

// ---------------------------------------------------------------------------
// Kernel 2: fp64 reduce of sum(W) and sum(|W|)
// ---------------------------------------------------------------------------
__global__ void reduce_w_kernel(const float* __restrict__ w) {
    int tid = threadIdx.x;
    int base = blockIdx.x * 1024 + tid;
    double s = 0.0, sa = 0.0;
#pragma unroll
    for (int j = 0; j < 4; ++j) {
        float v = w[base + j * 256];
        s  += (double)v;
        sa += (double)fabsf(v);
    }
#pragma unroll
    for (int off = 16; off > 0; off >>= 1) {
        s  += __shfl_down_sync(0xffffffffu, s,  off);
        sa += __shfl_down_sync(0xffffffffu, sa, off);
    }
    __shared__ double sh_s[8], sh_sa[8];
    int wid = tid >> 5, lane = tid & 31;
    if (lane == 0) { sh_s[wid] = s; sh_sa[wid] = sa; }
    __syncthreads();
    if (tid == 0) {
        double ts = 0.0, tsa = 0.0;
#pragma unroll
        for (int i = 0; i < 8; ++i) { ts += sh_s[i]; tsa += sh_sa[i]; }
        atomicAdd(&g_sum_w, ts);
        atomicAdd(&g_sum_absw, tsa);
    }
}

// ---------------------------------------------------------------------------
// Kernel 3: build transposed sign matrix in bf16 (no duplication)
// W is [K=512][N=512] row-major.
// ---------------------------------------------------------------------------
__global__ void build_bt_kernel(const float* __restrict__ w) {
    int idx = blockIdx.x * blockDim.x + threadIdx.x;   // 0..262143
    float mean = (float)(g_sum_w * (1.0 / 262144.0));
    float d = w[idx] - mean;
    float s = (d > 0.0f) ? 1.0f : ((d < 0.0f) ? -1.0f : 0.0f);
    int k = idx >> 9;      // in-feature index
    int n = idx & 511;     // out-feature index
    g_Bt[n * KF + k] = __float2bfloat16_rn(s);
}

// ---------------------------------------------------------------------------
// Quantization epilogue: mirrors reference arithmetic exactly
// ---------------------------------------------------------------------------
__device__ __forceinline__ float quant_out(float y) {
    float t = fminf(fmaxf(y, -1.0f), 1.0f);
    float q = rintf(t * 7.0f) / 7.0f;
    return y + (q - y);
}

// ---------------------------------------------------------------------------
// Kernel 4: split-bf16 GEMM + quant epilogue, B-fragment reuse across planes.
//   y = x_hi @ S + x_lo @ S   (S loaded once per k16, two mma passes)
//   CTA tile 128x128, per-iter 32 fp32 k, 2-stage ping-pong, 1 sync/iter.
//   8 warps, warp tile 32x64, mma.m16n8k16 bf16.
// ---------------------------------------------------------------------------
__global__ __launch_bounds__(256, 2)
void bitlinear_gemm_kernel(const float* __restrict__ x,
                           const float* __restrict__ bias,
                           float* __restrict__ out) {
    extern __shared__ char smem[];

    int bid = blockIdx.x;         // n-tile fastest for L2 x-reuse
    int m0 = (bid >> 2) << 7;
    int n0 = (bid & 3) << 7;

    int tid   = threadIdx.x;
    int wid   = tid >> 5;
    int lane  = tid & 31;
    int wm    = wid & 3;          // warp m-tile: rows wm*32 .. +31
    int wn    = wid >> 2;         // warp n-tile: cols wn*64 .. +63
    int group = lane >> 2;        // 0..7
    int tq    = lane & 3;         // 0..3

    float acc[2][8][4];
#pragma unroll
    for (int i = 0; i < 2; ++i)
#pragma unroll
        for (int j = 0; j < 8; ++j)
#pragma unroll
            for (int r = 0; r < 4; ++r) acc[i][j][r] = 0.0f;

    // ---- loader mappings ----
    // A: 2 threads per row, each covers 16 consecutive fp32 k
    int arow = tid >> 1;
    int aseg = tid & 1;
    const float* xg = x + (size_t)(m0 + arow) * KF + aseg * 16;
    // A smem store offsets (bytes within a plane)
    uint32_t a_st = (uint32_t)(arow * ROWB + aseg * 32);

    // B: 2 threads per row, each covers 16 consecutive bf16 k (32B)
    int brow = tid >> 1;
    int bseg = tid & 1;
    const __nv_bfloat16* btg = g_Bt + (size_t)(n0 + brow) * KF + bseg * 16;
    uint32_t b_st = (uint32_t)(brow * ROWB + bseg * 32);

    uint32_t smem_base = (uint32_t)__cvta_generic_to_shared(smem);

    // ldmatrix lane address patterns (rows within CTA tile, cols in u32 units)
    int a_lm_row = wm * 32 + (lane & 7) + ((lane >> 3) & 1) * 8;  // + mt*16
    int a_lm_col = (lane >> 4) * 4;                                // + s*8
    int b_lm_row = wn * 64 + ((lane >> 4) & 1) * 8 + (lane & 7);   // + ntp*16
    int b_lm_col = ((lane >> 3) & 1) * 4;                          // + s*8

    // ---- producer helpers ----
    auto load_a = [&](int kt, float4& f0, float4& f1, float4& f2, float4& f3) {
        const float4* xr = (const float4*)(xg + kt * 32);
        f0 = xr[0]; f1 = xr[1]; f2 = xr[2]; f3 = xr[3];
    };
    auto issue_b = [&](int stage, int kt) {
        uint32_t dst = smem_base + SB_OFF(stage) + b_st;
        const char* src = (const char*)(btg + (size_t)kt * 32);
        asm volatile("cp.async.cg.shared.global [%0], [%1], 16;"
                     :: "r"(dst), "l"(src));
        asm volatile("cp.async.cg.shared.global [%0], [%1], 16;"
                     :: "r"(dst + 16), "l"(src + 16));
        asm volatile("cp.async.commit_group;");
    };
    auto store_a = [&](int stage, float4 f0, float4 f1, float4 f2, float4 f3) {
        float fv[16] = {f0.x, f0.y, f0.z, f0.w, f1.x, f1.y, f1.z, f1.w,
                        f2.x, f2.y, f2.z, f2.w, f3.x, f3.y, f3.z, f3.w};
        uint32_t whi[8], wlo[8];
#pragma unroll
        for (int j = 0; j < 8; ++j) {
            float v0 = fv[2 * j], v1 = fv[2 * j + 1];
            __nv_bfloat16 h0 = __float2bfloat16_rn(v0);
            __nv_bfloat16 h1 = __float2bfloat16_rn(v1);
            float r0 = v0 - __bfloat162float(h0);
            float r1 = v1 - __bfloat162float(h1);
            __nv_bfloat16 l0 = __float2bfloat16_rn(r0);
            __nv_bfloat16 l1 = __float2bfloat16_rn(r1);
            whi[j] = ((uint32_t)__bfloat16_as_ushort(h1) << 16) |
                     (uint32_t)__bfloat16_as_ushort(h0);
            wlo[j] = ((uint32_t)__bfloat16_as_ushort(l1) << 16) |
                     (uint32_t)__bfloat16_as_ushort(l0);
        }
        char* hi = smem + SA_OFF(stage, 0) + a_st;
        char* lo = smem + SA_OFF(stage, 1) + a_st;
        *(uint4*)(hi)      = make_uint4(whi[0], whi[1], whi[2], whi[3]);
        *(uint4*)(hi + 16) = make_uint4(whi[4], whi[5], whi[6], whi[7]);
        *(uint4*)(lo)      = make_uint4(wlo[0], wlo[1], wlo[2], wlo[3]);
        *(uint4*)(lo + 16) = make_uint4(wlo[4], wlo[5], wlo[6], wlo[7]);
    };

    // ---- prologue: fill stage 0 ----
    {
        float4 f0, f1, f2, f3;
        load_a(0, f0, f1, f2, f3);
        issue_b(0, 0);
        store_a(0, f0, f1, f2, f3);
    }

    for (int kt = 0; kt < N_ITERS; ++kt) {
        int cur = kt & 1;
        int nxt = cur ^ 1;

        asm volatile("cp.async.wait_group 0;" ::: "memory");
        __syncthreads();   // stage `cur` ready; prior reads of `nxt` done

        // ---- issue next iteration's global loads early ----
        float4 f0, f1, f2, f3;
        if (kt < N_ITERS - 1) {
            load_a(kt + 1, f0, f1, f2, f3);
            issue_b(nxt, kt + 1);
        }

        uint32_t a_hi_base = smem_base + SA_OFF(cur, 0);
        uint32_t a_lo_base = smem_base + SA_OFF(cur, 1);
        uint32_t b_base    = smem_base + SB_OFF(cur);

        // ---- compute: 2 k16 steps, B frags reused for hi and lo planes ----
#pragma unroll
        for (int s = 0; s < 2; ++s) {
            // B fragments (4x ldmatrix.x4 -> 8 n-frags of 2 regs)
            uint32_t bf[8][2];
#pragma unroll
            for (int ntp = 0; ntp < 4; ++ntp) {
                uint32_t addr = b_base +
                    (uint32_t)((b_lm_row + ntp * 16) * ROWB +
                               (b_lm_col + s * 8) * 4);
                uint32_t r0, r1, r2, r3;
                asm volatile(
                    "ldmatrix.sync.aligned.m8n8.x4.shared.b16 {%0,%1,%2,%3}, [%4];\n"
                    : "=r"(r0), "=r"(r1), "=r"(r2), "=r"(r3)
                    : "r"(addr));
                bf[2 * ntp][0]     = r0;
                bf[2 * ntp][1]     = r1;
                bf[2 * ntp + 1][0] = r2;
                bf[2 * ntp + 1][1] = r3;
            }
            // hi plane pass, then lo plane pass (same B frags)
#pragma unroll
            for (int pl = 0; pl < 2; ++pl) {
                uint32_t plane_base = pl ? a_lo_base : a_hi_base;
                uint32_t af[2][4];
#pragma unroll
                for (int mt = 0; mt < 2; ++mt) {
                    uint32_t addr = plane_base +
                        (uint32_t)((a_lm_row + mt * 16) * ROWB +
                                   (a_lm_col + s * 8) * 4);
                    asm volatile(
                        "ldmatrix.sync.aligned.m8n8.x4.shared.b16 {%0,%1,%2,%3}, [%4];\n"
                        : "=r"(af[mt][0]), "=r"(af[mt][1]),
                          "=r"(af[mt][2]), "=r"(af[mt][3])
                        : "r"(addr));
                }
#pragma unroll
                for (int nt = 0; nt < 8; ++nt) {
#pragma unroll
                    for (int mt = 0; mt < 2; ++mt) {
                        asm volatile(
                            "mma.sync.aligned.m16n8k16.row.col.f32.bf16.bf16.f32 "
                            "{%0,%1,%2,%3}, {%4,%5,%6,%7}, {%8,%9}, {%0,%1,%2,%3};\n"
                            : "+f"(acc[mt][nt][0]), "+f"(acc[mt][nt][1]),
                              "+f"(acc[mt][nt][2]), "+f"(acc[mt][nt][3])
                            : "r"(af[mt][0]), "r"(af[mt][1]),
                              "r"(af[mt][2]), "r"(af[mt][3]),
                              "r"(bf[nt][0]), "r"(bf[nt][1]));
                    }
                }
            }
        }

        // ---- convert + store A for next iteration into stage `nxt` ----
        if (kt < N_ITERS - 1)
            store_a(nxt, f0, f1, f2, f3);
    }

    // ---- epilogue: scale by gamma, add bias, quantize, store ----
    float gamma = (float)(g_sum_absw * (1.0 / 262144.0));
#pragma unroll
    for (int mt = 0; mt < 2; ++mt) {
#pragma unroll
        for (int nt = 0; nt < 8; ++nt) {
            int row = m0 + wm * 32 + mt * 16 + group;
            int col = n0 + wn * 64 + nt * 8 + tq * 2;
            float bv0 = bias[col];
            float bv1 = bias[col + 1];
            float y0 = gamma * acc[mt][nt][0] + bv0;
            float y1 = gamma * acc[mt][nt][1] + bv1;
            float y2 = gamma * acc[mt][nt][2] + bv0;
            float y3 = gamma * acc[mt][nt][3] + bv1;
            float2* o0 = (float2*)(out + (size_t)row * NF + col);
            *o0 = make_float2(quant_out(y0), quant_out(y1));
            float2* o1 = (float2*)(out + (size_t)(row + 8) * NF + col);
            *o1 = make_float2(quant_out(y2), quant_out(y3));
        }
    }
}

// ---------------------------------------------------------------------------
// Launch: zero stats -> fp64 reduce -> build sign matrix -> GEMM+quant
// ---------------------------------------------------------------------------
extern "C" void kernel_launch(void* const* d_in, const int* in_sizes, int n_in,
                              void* d_out, int out_size) {
    const float* x = nullptr;
    const float* w = nullptr;
    const float* b = nullptr;
    for (int i = 0; i < n_in; ++i) {
        if (in_sizes[i] == M_TOTAL * KF)      x = (const float*)d_in[i];
        else if (in_sizes[i] == W_ELEMS)      w = (const float*)d_in[i];
        else if (in_sizes[i] == NF)           b = (const float*)d_in[i];
    }
    float* out = (float*)d_out;

    static int configured = 0;
    if (!configured) {
        cudaFuncSetAttribute(bitlinear_gemm_kernel,
                             cudaFuncAttributeMaxDynamicSharedMemorySize, SM_TOTAL);
        configured = 1;
    }

    zero_stats_kernel<<<1, 1>>>();
    reduce_w_kernel<<<256, 256>>>(w);
    build_bt_kernel<<<W_ELEMS / 256, 256>>>(w);
    bitlinear_gemm_kernel<<<(M_TOTAL / 128) * (NF / 128), 256, SM_TOTAL>>>(x, b, out);
}